// round 10
// baseline (speedup 1.0000x reference)
#include <cuda_runtime.h>
#include <cfloat>

#define POOL 7
#define SCALE 0.0625f
#define CHANS 256
#define FH 224
#define FW 224
#define FHW (FH * FW)
#define N_ROIS 512

// Replicate XLA-GPU's fp32 division (approximate, NOT correctly rounded).
// This exact op is what makes rel_err == 0 vs the reference. DO NOT CHANGE.
__device__ __forceinline__ float div_full(float a, float b) {
    float r; asm("div.full.f32 %0, %1, %2;" : "=f"(r) : "f"(a), "f"(b)); return r;
}
// round_half_up(v * 0.0625) — exact in fp32 for the input range
__device__ __forceinline__ int rhus(float v) {
    return (int)floorf(__fadd_rn(__fmul_rn(v, SCALE), 0.5f));
}
__device__ __forceinline__ float4 fmax4(float4 a, float4 b) {
    return make_float4(fmaxf(a.x, b.x), fmaxf(a.y, b.y),
                       fmaxf(a.z, b.z), fmaxf(a.w, b.w));
}

// One warp per (roi, channel-PAIR). Both channels share identical bin
// geometry -> prologue/epilogue/sync amortize 2x, and the two channel
// planes give 2 independent LDG streams for MLP.
__global__ void __launch_bounds__(128, 10) roipool_v7_kernel(
    const float* __restrict__ feat,
    const float* __restrict__ rois,
    float* __restrict__ out)
{
    __shared__ float smf[4][2][256];
    const int warp = threadIdx.x >> 5;
    const int lane = threadIdx.x & 31;
    const int cp = blockIdx.x >> 7;                  // channel pair 0..127 (slowest -> L2-resident)
    const int n  = ((blockIdx.x & 127) << 2) + warp; // 4 rois per block
    const int c0 = cp << 1;

    const float* roi = rois + n * 5;
    const int b  = (int)roi[0];
    const int xs = rhus(roi[1]);
    const int ys = rhus(roi[2]);
    const int xe = rhus(roi[3]);
    const int ye = rhus(roi[4]);
    const int roi_w = max(xe - xs + 1, 1);
    const int roi_h = max(ye - ys + 1, 1);
    const float bin_h = div_full((float)roi_h, 7.0f);
    const float bin_w = div_full((float)roi_w, 7.0f);

    // Lane p (p<7) computes pw-bin p's exact clipped column range.
    const float pf = (float)lane;
    const int wsp = min(max((int)floorf(__fmul_rn(pf,        bin_w)) + xs, 0), FW);
    const int wep = min(max((int)ceilf (__fmul_rn(pf + 1.0f, bin_w)) + xs, 0), FW);
    // Workspace end = lane 6's clipped bin end (monotone max; can exceed
    // xs+roi_w due to div.full rounding — load-bearing for bit-exactness).
    const int wlimit = __shfl_sync(0xffffffffu, wep, 6);
    const int xs4  = xs & ~3;                        // 16B-aligned base
    const int ns4  = max(0, (wlimit - xs4 + 127) >> 7);
    const bool two = ns4 > 1;
    const int col0 = xs4 + (lane << 2);
    const bool pr0 = (ns4 > 0) && (col0 < wlimit);   // start<wlimit<=224 -> in-row
    const bool pr1 = two && (col0 + 128 < wlimit);

    // Epilogue: 2 lanes per (bin, channel): lane<28, ch=lane/14, q=lane%14,
    // p=q>>1, j=q&1. Bin geometry is channel-invariant.
    const int ech = lane >= 14;
    const int q   = lane - 14 * ech;
    const int ep  = q >> 1;
    const int ej  = q & 1;
    const bool eact = lane < 28;
    const int es = __shfl_sync(0xffffffffu, wsp, ep);
    const int ee = __shfl_sync(0xffffffffu, wep, ep);
    const bool ewv = es < ee;

    const float* fA = feat + ((long long)b * CHANS + c0) * FHW;
    const float* fB = fA + FHW;
    float* oA = out + ((n * CHANS + c0) * POOL) * POOL;
    const float NEG = -FLT_MAX;
    float* eout = oA + ech * (POOL * POOL);          // per-lane output row base

    for (int ph = 0; ph < POOL; ++ph) {
        const float phf = (float)ph;
        const int hs = min(max((int)floorf(__fmul_rn(phf,        bin_h)) + ys, 0), FH);
        const int he = min(max((int)ceilf (__fmul_rn(phf + 1.0f, bin_h)) + ys, 0), FH);

        float4 aA = make_float4(NEG, NEG, NEG, NEG), aB = aA;
        float4 bA = aA, bB = aA;
        const long long off0 = (long long)hs * FW + col0;
        const float* rA = fA + off0;
        const float* rB = fB + off0;
        int h = hs;
        if (two) {
            // dual-strip (rare): 4 independent LDGs (2 strips x 2 ch), no row unroll
            for (; h < he; ++h, rA += FW, rB += FW) {
                float4 vA, vB, wA, wB;
                if (pr0) { vA = __ldg((const float4*)rA);
                           vB = __ldg((const float4*)rB); }
                if (pr1) { wA = __ldg((const float4*)(rA + 128));
                           wB = __ldg((const float4*)(rB + 128)); }
                if (pr0) { aA = fmax4(aA, vA); aB = fmax4(aB, vB); }
                if (pr1) { bA = fmax4(bA, wA); bB = fmax4(bB, wB); }
            }
        } else {
            // single-strip fast path: 2-row unroll x 2 ch = 4 LDGs in flight
            float4 a1A = aA, a1B = aA;
            for (; h + 1 < he; h += 2, rA += 2 * FW, rB += 2 * FW) {
                float4 vA0, vA1, vB0, vB1;
                if (pr0) { vA0 = __ldg((const float4*)rA);
                           vB0 = __ldg((const float4*)rB);
                           vA1 = __ldg((const float4*)(rA + FW));
                           vB1 = __ldg((const float4*)(rB + FW)); }
                if (pr0) { aA = fmax4(aA, vA0); aB = fmax4(aB, vB0);
                           a1A = fmax4(a1A, vA1); a1B = fmax4(a1B, vB1); }
            }
            if (h < he && pr0) {
                aA = fmax4(aA, __ldg((const float4*)rA));
                aB = fmax4(aB, __ldg((const float4*)rB));
            }
            aA = fmax4(aA, a1A);
            aB = fmax4(aB, a1B);
        }

        __syncwarp();                       // protect prev iteration's reads
        ((float4*)smf[warp][0])[lane] = aA;
        ((float4*)smf[warp][1])[lane] = aB;
        if (two) {
            ((float4*)smf[warp][0])[32 + lane] = bA;
            ((float4*)smf[warp][1])[32 + lane] = bB;
        }
        __syncwarp();

        // Parallel epilogue: 2 lanes stride bin ep's columns (both channels)
        float v = NEG;
        if (eact) {
            const float* s = smf[warp][ech];
            for (int col = es + ej; col < ee; col += 2)
                v = fmaxf(v, s[col - xs4]);
        }
        v = fmaxf(v, __shfl_xor_sync(0xffffffffu, v, 1));
        if (eact && ej == 0)
            eout[ph * POOL + ep] = (hs < he && ewv) ? v : 0.0f;
    }
}

extern "C" void kernel_launch(void* const* d_in, const int* in_sizes, int n_in,
                              void* d_out, int out_size) {
    const float* feat;
    const float* rois;
    if (in_sizes[0] > in_sizes[1]) {
        feat = (const float*)d_in[0];
        rois = (const float*)d_in[1];
    } else {
        feat = (const float*)d_in[1];
        rois = (const float*)d_in[0];
    }
    float* out = (float*)d_out;

    // 128 channel-pairs x 128 roi-groups; 4 warps (=4 rois) per block
    int blocks = (CHANS / 2) * (N_ROIS / 4);   // 16384
    roipool_v7_kernel<<<blocks, 128>>>(feat, rois, out);
}

// round 11
// speedup vs baseline: 1.5263x; 1.5263x over previous
#include <cuda_runtime.h>
#include <cfloat>

#define POOL 7
#define SCALE 0.0625f
#define CHANS 256
#define FH 224
#define FW 224
#define N_ROIS 512

// Replicate XLA-GPU's fp32 division (approximate, NOT correctly rounded).
// This exact op is what makes rel_err == 0 vs the reference. DO NOT CHANGE.
__device__ __forceinline__ float div_full(float a, float b) {
    float r; asm("div.full.f32 %0, %1, %2;" : "=f"(r) : "f"(a), "f"(b)); return r;
}
// round_half_up(v * 0.0625) — exact in fp32 for the input range
__device__ __forceinline__ int rhus(float v) {
    return (int)floorf(__fadd_rn(__fmul_rn(v, SCALE), 0.5f));
}
__device__ __forceinline__ float4 fmax4(float4 a, float4 b) {
    return make_float4(fmaxf(a.x, b.x), fmaxf(a.y, b.y),
                       fmaxf(a.z, b.z), fmaxf(a.w, b.w));
}

// One warp per (roi, channel). Lane covers 4 consecutive columns (float4);
// strip base 128B-ALIGNED so each warp LDG.128 covers exactly 4 L1 lines.
// Column maxes go to SMEM; epilogue = 4 lanes per pw-bin + 2-step shfl.
__global__ void __launch_bounds__(128, 12) roipool_v8_kernel(
    const float* __restrict__ feat,
    const float* __restrict__ rois,
    float* __restrict__ out)
{
    __shared__ float smf[4][256];
    const int warp = threadIdx.x >> 5;
    const int lane = threadIdx.x & 31;
    const int c = blockIdx.x >> 7;                   // channel slowest -> L2-resident slice
    const int n = ((blockIdx.x & 127) << 2) + warp;  // 4 rois per block

    const float* roi = rois + n * 5;
    const int b  = (int)roi[0];
    const int xs = rhus(roi[1]);
    const int ys = rhus(roi[2]);
    const int xe = rhus(roi[3]);
    const int ye = rhus(roi[4]);
    const int roi_w = max(xe - xs + 1, 1);
    const int roi_h = max(ye - ys + 1, 1);
    const float bin_h = div_full((float)roi_h, 7.0f);
    const float bin_w = div_full((float)roi_w, 7.0f);

    // Lane p (p<7) computes pw-bin p's exact clipped column range.
    const float pf = (float)lane;
    const int wsp = min(max((int)floorf(__fmul_rn(pf,        bin_w)) + xs, 0), FW);
    const int wep = min(max((int)ceilf (__fmul_rn(pf + 1.0f, bin_w)) + xs, 0), FW);
    // Workspace end = lane 6's clipped bin end (monotone max; can exceed
    // xs+roi_w due to div.full rounding — load-bearing for bit-exactness).
    const int wlimit = __shfl_sync(0xffffffffu, wep, 6);
    const int xs32 = xs & ~31;                       // 128B-aligned strip base
    const int ns   = max(0, (wlimit - xs32 + 127) >> 7);   // 0..2 strips (span<=253)
    const bool two = ns > 1;
    const int col0 = xs32 + (lane << 2);
    const bool pr0 = (ns > 0) && (col0 < wlimit);    // wlimit<=224 -> col0<=220, in-row
    const bool pr1 = two && (col0 + 128 < wlimit);

    // Epilogue assignment: 4 lanes per bin, p = lane>>2, j = lane&3.
    const int ep = lane >> 2;                        // 0..7 (7 -> idle)
    const int ej = lane & 3;
    const int es = __shfl_sync(0xffffffffu, wsp, ep & 7);
    const int ee = __shfl_sync(0xffffffffu, wep, ep & 7);
    const bool eact = (ep < POOL);
    const bool ewv  = eact && (es < ee);

    const float* fmap = feat + ((long long)b * CHANS + c) * (FH * FW);
    float* orow = out + ((n * CHANS + c) * POOL) * POOL;
    const float NEG = -FLT_MAX;

    for (int ph = 0; ph < POOL; ++ph) {
        const float phf = (float)ph;
        const int hs = min(max((int)floorf(__fmul_rn(phf,        bin_h)) + ys, 0), FH);
        const int he = min(max((int)ceilf (__fmul_rn(phf + 1.0f, bin_h)) + ys, 0), FH);

        float4 a0 = make_float4(NEG, NEG, NEG, NEG), a1 = a0, b0 = a0, b1 = a0;
        const float* r = fmap + hs * FW + col0;
        int h = hs;
        if (two) {   // dual-strip path (rare), 2-deep unroll
            for (; h + 1 < he; h += 2, r += 2 * FW) {
                float4 v0, v1, w0, w1;
                if (pr0) { v0 = __ldg((const float4*)r);
                           v1 = __ldg((const float4*)(r + FW)); }
                if (pr1) { w0 = __ldg((const float4*)(r + 128));
                           w1 = __ldg((const float4*)(r + 128 + FW)); }
                if (pr0) { a0 = fmax4(a0, v0); a1 = fmax4(a1, v1); }
                if (pr1) { b0 = fmax4(b0, w0); b1 = fmax4(b1, w1); }
            }
            if (h < he) {
                if (pr0) a0 = fmax4(a0, __ldg((const float4*)r));
                if (pr1) b0 = fmax4(b0, __ldg((const float4*)(r + 128)));
            }
        } else {     // single-strip fast path, 4-deep unroll (4 LDG in flight)
            for (; h + 3 < he; h += 4, r += 4 * FW) {
                float4 v0, v1, v2, v3;
                if (pr0) { v0 = __ldg((const float4*)r);
                           v1 = __ldg((const float4*)(r + FW));
                           v2 = __ldg((const float4*)(r + 2 * FW));
                           v3 = __ldg((const float4*)(r + 3 * FW)); }
                if (pr0) { a0 = fmax4(a0, v0); a1 = fmax4(a1, v1);
                           a0 = fmax4(a0, v2); a1 = fmax4(a1, v3); }
            }
            for (; h < he; ++h, r += FW)
                if (pr0) a0 = fmax4(a0, __ldg((const float4*)r));
        }
        a0 = fmax4(a0, a1);
        b0 = fmax4(b0, b1);

        __syncwarp();                       // protect prev iteration's reads
        ((float4*)smf[warp])[lane] = a0;    // cols [xs32 .. xs32+127]
        if (two) ((float4*)smf[warp])[32 + lane] = b0;  // cols [xs32+128 ..]
        __syncwarp();

        // Parallel epilogue: 4 lanes stride bin ep's columns by 4
        float v = NEG;
        if (eact) {
            for (int col = es + ej; col < ee; col += 4)
                v = fmaxf(v, smf[warp][col - xs32]);
        }
        v = fmaxf(v, __shfl_xor_sync(0xffffffffu, v, 1));
        v = fmaxf(v, __shfl_xor_sync(0xffffffffu, v, 2));
        if (eact && ej == 0)
            orow[ph * POOL + ep] = (hs < he && ewv) ? v : 0.0f;
    }
}

extern "C" void kernel_launch(void* const* d_in, const int* in_sizes, int n_in,
                              void* d_out, int out_size) {
    const float* feat;
    const float* rois;
    if (in_sizes[0] > in_sizes[1]) {
        feat = (const float*)d_in[0];
        rois = (const float*)d_in[1];
    } else {
        feat = (const float*)d_in[1];
        rois = (const float*)d_in[0];
    }
    float* out = (float*)d_out;

    // 128 blocks per channel x 256 channels; 4 warps (=4 rois) per block
    int blocks = CHANS * (N_ROIS / 4);   // 32768
    roipool_v8_kernel<<<blocks, 128>>>(feat, rois, out);
}

// round 12
// speedup vs baseline: 2.2451x; 1.4709x over previous
#include <cuda_runtime.h>
#include <cfloat>

#define POOL 7
#define SCALE 0.0625f
#define CHANS 256
#define FH 224
#define FW 224
#define N_ROIS 512

// Replicate XLA-GPU's fp32 division (approximate, NOT correctly rounded).
// This exact op is what makes rel_err == 0 vs the reference. DO NOT CHANGE.
__device__ __forceinline__ float div_full(float a, float b) {
    float r; asm("div.full.f32 %0, %1, %2;" : "=f"(r) : "f"(a), "f"(b)); return r;
}
// round_half_up(v * 0.0625) — exact in fp32 for the input range
__device__ __forceinline__ int rhus(float v) {
    return (int)floorf(__fadd_rn(__fmul_rn(v, SCALE), 0.5f));
}
__device__ __forceinline__ float4 fmax4(float4 a, float4 b) {
    return make_float4(fmaxf(a.x, b.x), fmaxf(a.y, b.y),
                       fmaxf(a.z, b.z), fmaxf(a.w, b.w));
}

// One warp per (roi, channel). Lane covers 4 consecutive columns (float4);
// strip base 128B-ALIGNED so each warp LDG.128 group covers exactly 4 L1
// lines (no straddle). NO reg-cap beyond 10 blocks/SM — forcing 12 spilled
// and doubled L1 traffic (R11). Epilogue = 4 lanes per pw-bin + 2-step shfl.
__global__ void __launch_bounds__(128, 10) roipool_v9_kernel(
    const float* __restrict__ feat,
    const float* __restrict__ rois,
    float* __restrict__ out)
{
    __shared__ float smf[4][256];
    const int warp = threadIdx.x >> 5;
    const int lane = threadIdx.x & 31;
    const int c = blockIdx.x >> 7;                   // channel slowest -> L2-resident slice
    const int n = ((blockIdx.x & 127) << 2) + warp;  // 4 rois per block

    const float* roi = rois + n * 5;
    const int b  = (int)roi[0];
    const int xs = rhus(roi[1]);
    const int ys = rhus(roi[2]);
    const int xe = rhus(roi[3]);
    const int ye = rhus(roi[4]);
    const int roi_w = max(xe - xs + 1, 1);
    const int roi_h = max(ye - ys + 1, 1);
    const float bin_h = div_full((float)roi_h, 7.0f);
    const float bin_w = div_full((float)roi_w, 7.0f);

    // Lane p (p<7) computes pw-bin p's exact clipped column range.
    const float pf = (float)lane;
    const int wsp = min(max((int)floorf(__fmul_rn(pf,        bin_w)) + xs, 0), FW);
    const int wep = min(max((int)ceilf (__fmul_rn(pf + 1.0f, bin_w)) + xs, 0), FW);
    // Workspace end = lane 6's clipped bin end (monotone max; can exceed
    // xs+roi_w due to div.full rounding — load-bearing for bit-exactness).
    const int wlimit = __shfl_sync(0xffffffffu, wep, 6);
    const int xs32 = xs & ~31;                       // 128B-aligned strip base
    const int ns   = max(0, (wlimit - xs32 + 127) >> 7);   // 0..2 strips (span<=255)
    const bool two = ns > 1;
    const int col0 = xs32 + (lane << 2);
    const bool pr0 = (ns > 0) && (col0 < wlimit);    // wlimit<=224 -> col0<=220, in-row
    const bool pr1 = two && (col0 + 128 < wlimit);

    // Epilogue assignment: 4 lanes per bin, p = lane>>2, j = lane&3.
    const int ep = lane >> 2;                        // 0..7 (7 -> idle)
    const int ej = lane & 3;
    const int es = __shfl_sync(0xffffffffu, wsp, ep & 7);
    const int ee = __shfl_sync(0xffffffffu, wep, ep & 7);
    const bool eact = (ep < POOL);
    const bool ewv  = eact && (es < ee);

    const float* fmap = feat + ((long long)b * CHANS + c) * (FH * FW);
    float* orow = out + ((n * CHANS + c) * POOL) * POOL;
    const float NEG = -FLT_MAX;

    for (int ph = 0; ph < POOL; ++ph) {
        const float phf = (float)ph;
        const int hs = min(max((int)floorf(__fmul_rn(phf,        bin_h)) + ys, 0), FH);
        const int he = min(max((int)ceilf (__fmul_rn(phf + 1.0f, bin_h)) + ys, 0), FH);

        float4 a0 = make_float4(NEG, NEG, NEG, NEG), a1 = a0, b0 = a0, b1 = a0;
        const float* r = fmap + hs * FW + col0;
        int h = hs;
        if (two) {   // dual-strip path, 2-deep unroll
            for (; h + 1 < he; h += 2, r += 2 * FW) {
                float4 v0, v1, w0, w1;
                if (pr0) { v0 = __ldg((const float4*)r);
                           v1 = __ldg((const float4*)(r + FW)); }
                if (pr1) { w0 = __ldg((const float4*)(r + 128));
                           w1 = __ldg((const float4*)(r + 128 + FW)); }
                if (pr0) { a0 = fmax4(a0, v0); a1 = fmax4(a1, v1); }
                if (pr1) { b0 = fmax4(b0, w0); b1 = fmax4(b1, w1); }
            }
            if (h < he) {
                if (pr0) a0 = fmax4(a0, __ldg((const float4*)r));
                if (pr1) b0 = fmax4(b0, __ldg((const float4*)(r + 128)));
            }
        } else {     // single-strip fast path, 4-deep unroll (4 LDG in flight)
            for (; h + 3 < he; h += 4, r += 4 * FW) {
                float4 v0, v1, v2, v3;
                if (pr0) { v0 = __ldg((const float4*)r);
                           v1 = __ldg((const float4*)(r + FW));
                           v2 = __ldg((const float4*)(r + 2 * FW));
                           v3 = __ldg((const float4*)(r + 3 * FW)); }
                if (pr0) { a0 = fmax4(a0, v0); a1 = fmax4(a1, v1);
                           a0 = fmax4(a0, v2); a1 = fmax4(a1, v3); }
            }
            for (; h < he; ++h, r += FW)
                if (pr0) a0 = fmax4(a0, __ldg((const float4*)r));
        }
        a0 = fmax4(a0, a1);
        b0 = fmax4(b0, b1);

        __syncwarp();                       // protect prev iteration's reads
        ((float4*)smf[warp])[lane] = a0;    // cols [xs32 .. xs32+127]
        if (two) ((float4*)smf[warp])[32 + lane] = b0;  // cols [xs32+128 ..]
        __syncwarp();

        // Parallel epilogue: 4 lanes stride bin ep's columns by 4
        float v = NEG;
        if (eact) {
            for (int col = es + ej; col < ee; col += 4)
                v = fmaxf(v, smf[warp][col - xs32]);
        }
        v = fmaxf(v, __shfl_xor_sync(0xffffffffu, v, 1));
        v = fmaxf(v, __shfl_xor_sync(0xffffffffu, v, 2));
        if (eact && ej == 0)
            orow[ph * POOL + ep] = (hs < he && ewv) ? v : 0.0f;
    }
}

extern "C" void kernel_launch(void* const* d_in, const int* in_sizes, int n_in,
                              void* d_out, int out_size) {
    const float* feat;
    const float* rois;
    if (in_sizes[0] > in_sizes[1]) {
        feat = (const float*)d_in[0];
        rois = (const float*)d_in[1];
    } else {
        feat = (const float*)d_in[1];
        rois = (const float*)d_in[0];
    }
    float* out = (float*)d_out;

    // 128 blocks per channel x 256 channels; 4 warps (=4 rois) per block
    int blocks = CHANS * (N_ROIS / 4);   // 32768
    roipool_v9_kernel<<<blocks, 128>>>(feat, rois, out);
}

// round 13
// speedup vs baseline: 2.3013x; 1.0251x over previous
#include <cuda_runtime.h>
#include <cfloat>

#define POOL 7
#define SCALE 0.0625f
#define CHANS 256
#define FH 224
#define FW 224
#define N_ROIS 512

// Replicate XLA-GPU's fp32 division (approximate, NOT correctly rounded).
// This exact op is what makes rel_err == 0 vs the reference. DO NOT CHANGE.
__device__ __forceinline__ float div_full(float a, float b) {
    float r; asm("div.full.f32 %0, %1, %2;" : "=f"(r) : "f"(a), "f"(b)); return r;
}
// round_half_up(v * 0.0625) — exact in fp32 for the input range
__device__ __forceinline__ int rhus(float v) {
    return (int)floorf(__fadd_rn(__fmul_rn(v, SCALE), 0.5f));
}
__device__ __forceinline__ float4 fmax4(float4 a, float4 b) {
    return make_float4(fmaxf(a.x, b.x), fmaxf(a.y, b.y),
                       fmaxf(a.z, b.z), fmaxf(a.w, b.w));
}

// One warp per (roi, channel). Three warp-uniform width modes:
//   narrow (span<=64):  2 rows x 16 lanes per iter  (half of all ROIs)
//   mid    (span<=128): 1 row  x 32 lanes, 4-deep row unroll
//   wide   (else):      2 strips x 2-deep row unroll
// Column maxes -> SMEM; epilogue = 4 lanes per pw-bin + 2-step shfl.
__global__ void __launch_bounds__(128, 10) roipool_v10_kernel(
    const float* __restrict__ feat,
    const float* __restrict__ rois,
    float* __restrict__ out)
{
    __shared__ float smf[4][256];
    const int warp = threadIdx.x >> 5;
    const int lane = threadIdx.x & 31;
    const int c = blockIdx.x >> 7;                   // channel slowest -> L2-resident slice
    const int n = ((blockIdx.x & 127) << 2) + warp;  // 4 rois per block

    const float* roi = rois + n * 5;
    const int b  = (int)roi[0];
    const int xs = rhus(roi[1]);
    const int ys = rhus(roi[2]);
    const int xe = rhus(roi[3]);
    const int ye = rhus(roi[4]);
    const int roi_w = max(xe - xs + 1, 1);
    const int roi_h = max(ye - ys + 1, 1);
    const float bin_h = div_full((float)roi_h, 7.0f);
    const float bin_w = div_full((float)roi_w, 7.0f);

    // Lane p (p<7) computes pw-bin p's exact clipped column range.
    const float pf = (float)lane;
    const int wsp = min(max((int)floorf(__fmul_rn(pf,        bin_w)) + xs, 0), FW);
    const int wep = min(max((int)ceilf (__fmul_rn(pf + 1.0f, bin_w)) + xs, 0), FW);
    // Workspace end = lane 6's clipped bin end (monotone max; can exceed
    // xs+roi_w due to div.full rounding — load-bearing for bit-exactness).
    const int wlimit = __shfl_sync(0xffffffffu, wep, 6);
    const int xs4  = xs & ~3;                        // 16B-aligned base
    const int span = wlimit - xs4;
    const bool narrow = span <= 64;
    const bool two    = span > 128;

    // Narrow-mode lane split: rlane = row offset (0/1), clane = column lane.
    const int rlane = lane >> 4;
    const int clane = lane & 15;

    const int col0  = xs4 + (lane << 2);             // mid/wide column base
    const int col0n = xs4 + (clane << 2);            // narrow column base
    const bool pr0 = (span > 0) && (col0 < wlimit);  // wlimit<=224 -> in-row
    const bool pr1 = two && (col0 + 128 < wlimit);
    const bool prn = (span > 0) && (col0n < wlimit);

    // Epilogue assignment: 4 lanes per bin, p = lane>>2, j = lane&3.
    const int ep = lane >> 2;                        // 0..7 (7 -> idle)
    const int ej = lane & 3;
    const int es = __shfl_sync(0xffffffffu, wsp, ep & 7);
    const int ee = __shfl_sync(0xffffffffu, wep, ep & 7);
    const bool eact = (ep < POOL);
    const bool ewv  = eact && (es < ee);

    const float* fmap = feat + ((long long)b * CHANS + c) * (FH * FW);
    float* orow = out + ((n * CHANS + c) * POOL) * POOL;
    const float NEG = -FLT_MAX;

    for (int ph = 0; ph < POOL; ++ph) {
        const float phf = (float)ph;
        const int hs = min(max((int)floorf(__fmul_rn(phf,        bin_h)) + ys, 0), FH);
        const int he = min(max((int)ceilf (__fmul_rn(phf + 1.0f, bin_h)) + ys, 0), FH);

        float4 a0 = make_float4(NEG, NEG, NEG, NEG), a1 = a0;

        if (narrow) {
            // 2 rows x 16 lanes; 4 rows per unrolled iter
            const float* r = fmap + (hs + rlane) * FW + col0n;
            int h = hs;
            for (; h + 3 < he; h += 4, r += 4 * FW) {
                float4 v0, v1;
                if (prn) { v0 = __ldg((const float4*)r);
                           v1 = __ldg((const float4*)(r + 2 * FW)); }
                if (prn) { a0 = fmax4(a0, v0); a1 = fmax4(a1, v1); }
            }
            for (; h < he; h += 2, r += 2 * FW) {     // tail: 0..3 rows
                if (prn && (h + rlane) < he)
                    a0 = fmax4(a0, __ldg((const float4*)r));
            }
            a0 = fmax4(a0, a1);
            // merge the two row-halves (lane L <-> L^16 hold same columns)
            a0.x = fmaxf(a0.x, __shfl_xor_sync(0xffffffffu, a0.x, 16));
            a0.y = fmaxf(a0.y, __shfl_xor_sync(0xffffffffu, a0.y, 16));
            a0.z = fmaxf(a0.z, __shfl_xor_sync(0xffffffffu, a0.z, 16));
            a0.w = fmaxf(a0.w, __shfl_xor_sync(0xffffffffu, a0.w, 16));

            __syncwarp();
            if (lane < 16) ((float4*)smf[warp])[clane] = a0;
            __syncwarp();
        } else if (!two) {
            // single strip, 4-deep row unroll
            const float* r = fmap + hs * FW + col0;
            int h = hs;
            for (; h + 3 < he; h += 4, r += 4 * FW) {
                float4 v0, v1, v2, v3;
                if (pr0) { v0 = __ldg((const float4*)r);
                           v1 = __ldg((const float4*)(r + FW));
                           v2 = __ldg((const float4*)(r + 2 * FW));
                           v3 = __ldg((const float4*)(r + 3 * FW)); }
                if (pr0) { a0 = fmax4(a0, v0); a1 = fmax4(a1, v1);
                           a0 = fmax4(a0, v2); a1 = fmax4(a1, v3); }
            }
            for (; h < he; ++h, r += FW)
                if (pr0) a0 = fmax4(a0, __ldg((const float4*)r));
            a0 = fmax4(a0, a1);

            __syncwarp();
            ((float4*)smf[warp])[lane] = a0;
            __syncwarp();
        } else {
            // dual strip, 2-deep row unroll
            float4 b0 = a0, b1 = a0;
            const float* r = fmap + hs * FW + col0;
            int h = hs;
            for (; h + 1 < he; h += 2, r += 2 * FW) {
                float4 v0, v1, w0, w1;
                if (pr0) { v0 = __ldg((const float4*)r);
                           v1 = __ldg((const float4*)(r + FW)); }
                if (pr1) { w0 = __ldg((const float4*)(r + 128));
                           w1 = __ldg((const float4*)(r + 128 + FW)); }
                if (pr0) { a0 = fmax4(a0, v0); a1 = fmax4(a1, v1); }
                if (pr1) { b0 = fmax4(b0, w0); b1 = fmax4(b1, w1); }
            }
            if (h < he) {
                if (pr0) a0 = fmax4(a0, __ldg((const float4*)r));
                if (pr1) b0 = fmax4(b0, __ldg((const float4*)(r + 128)));
            }
            a0 = fmax4(a0, a1);
            b0 = fmax4(b0, b1);

            __syncwarp();
            ((float4*)smf[warp])[lane] = a0;
            ((float4*)smf[warp])[32 + lane] = b0;
            __syncwarp();
        }

        // Parallel epilogue: 4 lanes stride bin ep's columns by 4
        float v = NEG;
        if (eact) {
            for (int col = es + ej; col < ee; col += 4)
                v = fmaxf(v, smf[warp][col - xs4]);
        }
        v = fmaxf(v, __shfl_xor_sync(0xffffffffu, v, 1));
        v = fmaxf(v, __shfl_xor_sync(0xffffffffu, v, 2));
        if (eact && ej == 0)
            orow[ph * POOL + ep] = (hs < he && ewv) ? v : 0.0f;
    }
}

extern "C" void kernel_launch(void* const* d_in, const int* in_sizes, int n_in,
                              void* d_out, int out_size) {
    const float* feat;
    const float* rois;
    if (in_sizes[0] > in_sizes[1]) {
        feat = (const float*)d_in[0];
        rois = (const float*)d_in[1];
    } else {
        feat = (const float*)d_in[1];
        rois = (const float*)d_in[0];
    }
    float* out = (float*)d_out;

    // 128 blocks per channel x 256 channels; 4 warps (=4 rois) per block
    int blocks = CHANS * (N_ROIS / 4);   // 32768
    roipool_v10_kernel<<<blocks, 128>>>(feat, rois, out);
}